// round 11
// baseline (speedup 1.0000x reference)
#include <cuda_runtime.h>
#include <cuda_bf16.h>
#include <cstdint>

// Problem constants (fixed by dataset)
#define BB    256      // batch
#define TT    1024     // timesteps
#define DX    64       // obs dim
#define DZ    256      // latent dim
#define DH    1024     // hidden dim
#define SS    16       // subjects
#define DF    64       // teacher-forced dims
#define ALPHA 0.2f

// -------- static device scratch (no allocation allowed) --------
__device__ float g_P64[DX * DF];                    // pinv(obs)[:, :64]  (64x64)
__device__ float g_forcing[(size_t)BB * TT * DF];   // 64 MB
__device__ float g_Z[(size_t)BB * TT * DZ];         // 256 MB latent trajectory

// ===================== Kernel A: pinv via normal equations =====================
// G = M^T M (64x64), Gauss-Jordan inverse (SPD, cond ~9 -> no pivoting needed),
// P64[i][j] = sum_k Ginv[i][k] * M[j][k]  for j < 64 (only first 64 pinv cols used).
__global__ void kpinv(const float* __restrict__ obs) {
    __shared__ float Gs[64 * 64];
    __shared__ float Au[64 * 64];
    __shared__ float fcol[64];
    __shared__ float s_piv;
    int tid = threadIdx.x;   // 256 threads

    for (int e = tid; e < 4096; e += 256) {
        int a = e >> 6, b = e & 63;
        float s = 0.f;
        for (int r = 0; r < DZ; ++r)
            s += obs[r * DX + a] * obs[r * DX + b];
        Gs[e] = s;
        Au[e] = (a == b) ? 1.f : 0.f;
    }
    __syncthreads();

    for (int c = 0; c < 64; ++c) {
        if (tid == 0) s_piv = 1.f / Gs[c * 64 + c];
        __syncthreads();
        if (tid < 128) {
            if (tid < 64) Gs[c * 64 + tid] *= s_piv;
            else          Au[c * 64 + (tid - 64)] *= s_piv;
        }
        __syncthreads();
        if (tid < 64) fcol[tid] = (tid == c) ? 0.f : Gs[tid * 64 + c];
        __syncthreads();
        for (int idx = tid; idx < 8192; idx += 256) {
            int r = idx >> 7, col = idx & 127;
            float f = fcol[r];
            if (f != 0.f) {
                if (col < 64) Gs[r * 64 + col]        -= f * Gs[c * 64 + col];
                else          Au[r * 64 + (col - 64)] -= f * Au[c * 64 + (col - 64)];
            }
        }
        __syncthreads();
    }

    for (int e = tid; e < 64 * DF; e += 256) {
        int i = e >> 6, j = e & 63;
        float s = 0.f;
        for (int k = 0; k < 64; ++k)
            s += Au[i * 64 + k] * obs[j * DX + k];
        g_P64[i * DF + j] = s;
    }
}

// ===================== Kernel B: forcing[:, :, :64] = x @ P64 =====================
__global__ void kforce(const float* __restrict__ x) {
    __shared__ float Ps[64 * 64];
    __shared__ float xs[4 * 64];
    int tid = threadIdx.x;  // 256
    for (int idx = tid; idx < 4096; idx += 256) Ps[idx] = g_P64[idx];
    size_t r0 = (size_t)blockIdx.x * 4;
    xs[tid] = x[r0 * DX + tid];
    __syncthreads();
    int rr = tid >> 6, j = tid & 63;
    float acc = 0.f;
    #pragma unroll
    for (int i = 0; i < 64; ++i)
        acc += xs[rr * 64 + i] * Ps[i * 64 + j];
    g_forcing[(r0 + rr) * DF + j] = acc;
}

// ===================== Kernel R: the recurrence (one CTA per batch) =====================
// Weights read DIRECTLY in their native reference layouts (no transposes):
//   W1: (S, dz=256, dh=1024)  row i contiguous over h
//   W2: (S, dh=1024, dz=256)  row h contiguous over k
// Phase 1: warp w, pass p -> output h = p*32+w; lanes split k (stride-1 coalesced),
//          shfl tree reduce, lane 0 writes hid[h] = relu(acc + h2[h]).
// Phase 2: warp w, pass p -> output i = p*32+w; lanes split h; lane 0 does
//          z[i] = A[i]*z[i] + acc + h1[i] and stores to g_Z.
__global__ void __launch_bounds__(1024)
krecur(const int* __restrict__ subject,
       const float* __restrict__ A_t,  const float* __restrict__ h1_t,
       const float* __restrict__ h2_t,
       const float* __restrict__ W1_t, const float* __restrict__ W2_t) {
    __shared__ float zs[DZ];
    __shared__ float hid[DH];
    __shared__ float As[DZ], h1s[DZ], h2s[DH];

    int b = blockIdx.x;              // one batch sample per CTA
    int s = subject[b];
    int tid = threadIdx.x;           // 1024
    int w = tid >> 5, l = tid & 31;  // warp id, lane id

    const float* w1 = W1_t + (size_t)s * DZ * DH;   // [i][h]
    const float* w2 = W2_t + (size_t)s * DH * DZ;   // [h][k]

    if (tid < DZ) {
        As[tid]  = A_t[s * DZ + tid];
        h1s[tid] = h1_t[s * DZ + tid];
        zs[tid]  = 0.f;              // z0 = 0 (forced dims set at t=0 below)
    }
    h2s[tid] = h2_t[s * DH + tid];
    __syncthreads();

    const size_t fbase = (size_t)b * TT * DF;
    const size_t zbase = (size_t)b * TT * DZ;

    for (int t = 0; t < TT; ++t) {
        // generalized teacher forcing on first DF dims.
        // t==0: z0[:DF]=f0, then 0.2*f0+0.8*f0 = f0 -> set f0 directly.
        if (tid < DF) {
            float fv = g_forcing[fbase + (size_t)t * DF + tid];
            zs[tid] = (t == 0) ? fv : (ALPHA * fv + (1.f - ALPHA) * zs[tid]);
        }
        __syncthreads();

        // ---- phase 1: hid[h] = relu( sum_k W2[h][k] * z[k] + h2[h] ) ----
        #pragma unroll 2
        for (int p = 0; p < 32; ++p) {
            int h = p * 32 + w;
            const float* row = w2 + (size_t)h * DZ + l;
            float acc = 0.f;
            #pragma unroll
            for (int j = 0; j < 8; ++j)
                acc += row[j * 32] * zs[l + j * 32];
            acc += __shfl_down_sync(0xffffffffu, acc, 16);
            acc += __shfl_down_sync(0xffffffffu, acc, 8);
            acc += __shfl_down_sync(0xffffffffu, acc, 4);
            acc += __shfl_down_sync(0xffffffffu, acc, 2);
            acc += __shfl_down_sync(0xffffffffu, acc, 1);
            if (l == 0) hid[h] = fmaxf(acc + h2s[h], 0.f);
        }
        __syncthreads();

        // ---- phase 2: z[i] = A[i]*z[i] + sum_h W1[i][h] * hid[h] + h1[i] ----
        #pragma unroll 2
        for (int p = 0; p < 8; ++p) {
            int i = p * 32 + w;
            const float* row = w1 + (size_t)i * DH + l;
            float acc = 0.f;
            #pragma unroll
            for (int j = 0; j < 32; ++j)
                acc += row[j * 32] * hid[l + j * 32];
            acc += __shfl_down_sync(0xffffffffu, acc, 16);
            acc += __shfl_down_sync(0xffffffffu, acc, 8);
            acc += __shfl_down_sync(0xffffffffu, acc, 4);
            acc += __shfl_down_sync(0xffffffffu, acc, 2);
            acc += __shfl_down_sync(0xffffffffu, acc, 1);
            if (l == 0) {
                float zn = As[i] * zs[i] + acc + h1s[i];
                zs[i] = zn;
                g_Z[zbase + (size_t)t * DZ + i] = zn;
            }
        }
        __syncthreads();
    }
}

// ===================== Kernel D: decode out = Z @ obs =====================
__global__ void kdecode(const float* __restrict__ obs, float* __restrict__ out) {
    extern __shared__ float smd[];
    float* obss = smd;               // DZ*64 = 16384 floats (64 KB)
    float* zsm  = obss + DZ * 64;    // 32*DZ =  8192 floats (32 KB)
    int tid = threadIdx.x;           // 512
    for (int idx = tid; idx < DZ * 64; idx += 512) obss[idx] = obs[idx];
    size_t r0 = (size_t)blockIdx.x * 32;
    for (int idx = tid; idx < 32 * DZ; idx += 512) zsm[idx] = g_Z[r0 * DZ + idx];
    __syncthreads();
    int g = tid & 15, j = tid >> 4;  // 16 x-groups of 4, 32 rows
    int x0 = g * 4;
    float4 acc = {0, 0, 0, 0};
    const float* zp = zsm + j * DZ;
    #pragma unroll 4
    for (int zi = 0; zi < DZ; ++zi) {
        float zv = zp[zi];
        float4 ov = *(const float4*)&obss[zi * 64 + x0];
        acc.x += zv * ov.x; acc.y += zv * ov.y; acc.z += zv * ov.z; acc.w += zv * ov.w;
    }
    *(float4*)&out[(r0 + j) * 64 + x0] = acc;
}

// ===================== host =====================
extern "C" void kernel_launch(void* const* d_in, const int* in_sizes, int n_in,
                              void* d_out, int out_size) {
    const float* x_gt  = (const float*)d_in[0];   // (256,1024,64)
    const int*   subj  = (const int*)  d_in[1];   // (256,)
    const float* obs   = (const float*)d_in[2];   // (256,64)
    const float* A_t   = (const float*)d_in[3];   // (16,256)
    const float* W1_t  = (const float*)d_in[4];   // (16,256,1024)
    const float* W2_t  = (const float*)d_in[5];   // (16,1024,256)
    const float* h1_t  = (const float*)d_in[6];   // (16,256)
    const float* h2_t  = (const float*)d_in[7];   // (16,1024)
    float* out = (float*)d_out;

    cudaFuncSetAttribute(kdecode, cudaFuncAttributeMaxDynamicSharedMemorySize, 98304);

    kpinv<<<1, 256>>>(obs);
    kforce<<<(BB * TT) / 4, 256>>>(x_gt);
    krecur<<<BB, 1024>>>(subj, A_t, h1_t, h2_t, W1_t, W2_t);
    kdecode<<<(BB * TT) / 32, 512, 98304>>>(obs, out);
}